// round 1
// baseline (speedup 1.0000x reference)
#include <cuda_runtime.h>
#include <math.h>

#define BATCH 32
#define SEQ   768
#define CDIM  256
#define HDIM  64
#define ROWS  (BATCH * SEQ)      // 24576
#define QTILES (SEQ / 64)        // 12

// Scratch for projected Q, K, V (no cudaMalloc allowed)
__device__ float g_q[ROWS * HDIM];
__device__ float g_k[ROWS * HDIM];
__device__ float g_v[ROWS * HDIM];

// ---------------------------------------------------------------------------
// Kernel 1: QKV projection.  out[r, h] = sum_c x[r, c] * w[c, h]
// Grid: (ROWS/64, 3).  Block: 256 threads.  64x64 output tile, K-tile = 64.
// ---------------------------------------------------------------------------
__global__ __launch_bounds__(256) void qkv_kernel(
    const float* __restrict__ x,
    const float* __restrict__ wq,
    const float* __restrict__ wk,
    const float* __restrict__ wv)
{
    __shared__ float xs[64][68];   // transposed: xs[c][r]
    __shared__ float ws[64][68];   // ws[c][h]

    const int tile  = blockIdx.x;          // row tile
    const int which = blockIdx.y;          // 0=q 1=k 2=v
    const float* __restrict__ w = (which == 0) ? wq : (which == 1) ? wk : wv;
    float* __restrict__ out = (which == 0) ? g_q : (which == 1) ? g_k : g_v;

    const int r0 = tile * 64;
    const int t  = threadIdx.x;
    const int tr = t >> 4;                 // 0..15
    const int tc = t & 15;                 // 0..15

    float acc[4][4] = {};

    for (int kk = 0; kk < CDIM; kk += 64) {
        __syncthreads();
        // load X tile (64 rows x 64 cols), store transposed
        #pragma unroll
        for (int rep = 0; rep < 4; rep++) {
            int idx = t + rep * 256;       // float4 index 0..1023
            int r   = idx >> 4;            // 0..63
            int c4  = (idx & 15) * 4;      // 0..60
            float4 xv = *(const float4*)&x[(size_t)(r0 + r) * CDIM + kk + c4];
            xs[c4 + 0][r] = xv.x;
            xs[c4 + 1][r] = xv.y;
            xs[c4 + 2][r] = xv.z;
            xs[c4 + 3][r] = xv.w;
        }
        // load W tile (64 x 64), natural layout
        #pragma unroll
        for (int rep = 0; rep < 4; rep++) {
            int idx = t + rep * 256;
            int k   = idx >> 4;
            int h4  = (idx & 15) * 4;
            *(float4*)&ws[k][h4] = *(const float4*)&w[(size_t)(kk + k) * HDIM + h4];
        }
        __syncthreads();

        #pragma unroll 16
        for (int k = 0; k < 64; k++) {
            float4 a = *(const float4*)&xs[k][tr * 4];
            float4 b = *(const float4*)&ws[k][tc * 4];
            float av[4] = {a.x, a.y, a.z, a.w};
            float bv[4] = {b.x, b.y, b.z, b.w};
            #pragma unroll
            for (int i = 0; i < 4; i++)
                #pragma unroll
                for (int j = 0; j < 4; j++)
                    acc[i][j] = fmaf(av[i], bv[j], acc[i][j]);
        }
    }

    #pragma unroll
    for (int i = 0; i < 4; i++) {
        float4 o = make_float4(acc[i][0], acc[i][1], acc[i][2], acc[i][3]);
        *(float4*)&out[(size_t)(r0 + tr * 4 + i) * HDIM + tc * 4] = o;
    }
}

// ---------------------------------------------------------------------------
// Kernel 2: causal flash attention, one CTA per (q-tile, batch).
// Block: 256 threads, 4x4 register tiles on a 16x16 thread grid.
// Dynamic smem: qs^T, ks^T, vs, ps^T  (4 * 64 * 68 floats = 69632 B)
// ---------------------------------------------------------------------------
__global__ __launch_bounds__(256) void attn_kernel(float* __restrict__ out)
{
    extern __shared__ float sm[];
    float (*qs)[68] = (float(*)[68])(sm);               // qs[h][i]
    float (*ks)[68] = (float(*)[68])(sm + 64 * 68);     // ks[h][j]
    float (*vs)[68] = (float(*)[68])(sm + 2 * 64 * 68); // vs[j][h]
    float (*ps)[68] = (float(*)[68])(sm + 3 * 64 * 68); // ps[j][i]

    const int qi = blockIdx.x;             // q tile 0..11
    const int b  = blockIdx.y;             // batch
    const int q0 = qi * 64;
    const int t  = threadIdx.x;
    const int tr = t >> 4;
    const int tc = t & 15;
    const float scale = 0.125f;            // 1/sqrt(64)

    // load Q tile transposed (once)
    #pragma unroll
    for (int rep = 0; rep < 4; rep++) {
        int idx = t + rep * 256;
        int r   = idx >> 4;
        int h4  = (idx & 15) * 4;
        float4 qv = *(const float4*)&g_q[(size_t)(b * SEQ + q0 + r) * HDIM + h4];
        qs[h4 + 0][r] = qv.x;
        qs[h4 + 1][r] = qv.y;
        qs[h4 + 2][r] = qv.z;
        qs[h4 + 3][r] = qv.w;
    }

    float o[4][4] = {};
    float m[4], l[4];
    #pragma unroll
    for (int i = 0; i < 4; i++) { m[i] = -1e30f; l[i] = 0.0f; }

    for (int kt = 0; kt <= qi; kt++) {
        __syncthreads();   // previous iteration's smem reads done (also covers Q load)

        // load K tile transposed and V tile natural
        const size_t kbase = (size_t)(b * SEQ + kt * 64) * HDIM;
        #pragma unroll
        for (int rep = 0; rep < 4; rep++) {
            int idx = t + rep * 256;
            int j   = idx >> 4;
            int h4  = (idx & 15) * 4;
            float4 kv = *(const float4*)&g_k[kbase + (size_t)j * HDIM + h4];
            ks[h4 + 0][j] = kv.x;
            ks[h4 + 1][j] = kv.y;
            ks[h4 + 2][j] = kv.z;
            ks[h4 + 3][j] = kv.w;
            float4 vv = *(const float4*)&g_v[kbase + (size_t)j * HDIM + h4];
            *(float4*)&vs[j][h4] = vv;
        }
        __syncthreads();

        // S = Q K^T (4x4 register tile)
        float s[4][4] = {};
        #pragma unroll 16
        for (int h = 0; h < 64; h++) {
            float4 a  = *(const float4*)&qs[h][tr * 4];
            float4 bb = *(const float4*)&ks[h][tc * 4];
            float av[4] = {a.x, a.y, a.z, a.w};
            float bv[4] = {bb.x, bb.y, bb.z, bb.w};
            #pragma unroll
            for (int i = 0; i < 4; i++)
                #pragma unroll
                for (int j = 0; j < 4; j++)
                    s[i][j] = fmaf(av[i], bv[j], s[i][j]);
        }

        // scale + causal mask (only diagonal tile needs it)
        const bool diag = (kt == qi);
        #pragma unroll
        for (int i = 0; i < 4; i++)
            #pragma unroll
            for (int j = 0; j < 4; j++) {
                float sv = s[i][j] * scale;
                if (diag && (tc * 4 + j) > (tr * 4 + i)) sv = -1e30f;
                s[i][j] = sv;
            }

        // row max over this tile (reduce across 16 tc threads in half-warp)
        float mt[4];
        #pragma unroll
        for (int i = 0; i < 4; i++)
            mt[i] = fmaxf(fmaxf(s[i][0], s[i][1]), fmaxf(s[i][2], s[i][3]));
        #pragma unroll
        for (int off = 1; off < 16; off <<= 1)
            #pragma unroll
            for (int i = 0; i < 4; i++)
                mt[i] = fmaxf(mt[i], __shfl_xor_sync(0xffffffffu, mt[i], off));

        float esc[4];
        #pragma unroll
        for (int i = 0; i < 4; i++) {
            float mn = fmaxf(m[i], mt[i]);
            esc[i] = __expf(m[i] - mn);
            m[i] = mn;
        }

        // p = exp(s - m), row sums
        float rs[4] = {};
        float p[4][4];
        #pragma unroll
        for (int i = 0; i < 4; i++)
            #pragma unroll
            for (int j = 0; j < 4; j++) {
                float pv = __expf(s[i][j] - m[i]);
                p[i][j] = pv;
                rs[i] += pv;
            }
        #pragma unroll
        for (int off = 1; off < 16; off <<= 1)
            #pragma unroll
            for (int i = 0; i < 4; i++)
                rs[i] += __shfl_xor_sync(0xffffffffu, rs[i], off);

        #pragma unroll
        for (int i = 0; i < 4; i++)
            l[i] = l[i] * esc[i] + rs[i];

        // rescale running O
        #pragma unroll
        for (int i = 0; i < 4; i++)
            #pragma unroll
            for (int c = 0; c < 4; c++)
                o[i][c] *= esc[i];

        // stage P transposed for the O GEMM
        #pragma unroll
        for (int i = 0; i < 4; i++)
            #pragma unroll
            for (int j = 0; j < 4; j++)
                ps[tc * 4 + j][tr * 4 + i] = p[i][j];
        __syncthreads();

        // O += P V
        #pragma unroll 16
        for (int j = 0; j < 64; j++) {
            float4 a  = *(const float4*)&ps[j][tr * 4];
            float4 bb = *(const float4*)&vs[j][tc * 4];
            float av[4] = {a.x, a.y, a.z, a.w};
            float bv[4] = {bb.x, bb.y, bb.z, bb.w};
            #pragma unroll
            for (int i = 0; i < 4; i++)
                #pragma unroll
                for (int c = 0; c < 4; c++)
                    o[i][c] = fmaf(av[i], bv[c], o[i][c]);
        }
    }

    // normalize + write
    #pragma unroll
    for (int i = 0; i < 4; i++) {
        float inv = 1.0f / l[i];
        float4 ov = make_float4(o[i][0] * inv, o[i][1] * inv, o[i][2] * inv, o[i][3] * inv);
        *(float4*)&out[(size_t)(b * SEQ + q0 + tr * 4 + i) * HDIM + tc * 4] = ov;
    }
}

// ---------------------------------------------------------------------------
extern "C" void kernel_launch(void* const* d_in, const int* in_sizes, int n_in,
                              void* d_out, int out_size)
{
    const float* x  = (const float*)d_in[0];
    const float* wq = (const float*)d_in[1];
    const float* wk = (const float*)d_in[2];
    const float* wv = (const float*)d_in[3];
    float* out = (float*)d_out;

    const int ATTN_SMEM = 4 * 64 * 68 * (int)sizeof(float);   // 69632 B
    cudaFuncSetAttribute(attn_kernel, cudaFuncAttributeMaxDynamicSharedMemorySize, ATTN_SMEM);

    qkv_kernel<<<dim3(ROWS / 64, 3), 256>>>(x, wq, wk, wv);
    attn_kernel<<<dim3(QTILES, BATCH), 256, ATTN_SMEM>>>(out);
}